// round 4
// baseline (speedup 1.0000x reference)
#include <cuda_runtime.h>
#include <cstdint>

#define N_DRUG 100000
#define N_DIS  100000
#define N_RDN  200000
#define HID    64
#define ERR_   1600000
#define EDD_   1600000
#define ERD_   3200000
#define FLAT_DRUG 6400000   // N_DRUG*HID
#define FLAT_ALL  12800000  // N_RDN*HID

// d_out layout (float32):
#define OFF_DRUGE  0
#define OFF_DISE   6400000
#define OFF_ALL    12800000   // drugAll then disAll (contiguous 12.8M)
#define OFF_RD     25600000   // rd_drug then rd_dis (== concat(emb))
#define OFF_META   38400000
#define OFF_STACK  38400001   // rd_stack [200000,4,64]

// -------- scratch (static device globals; no allocation allowed) --------
__device__ float g_cur_ds[FLAT_ALL];        // (cur_drug ; cur_dis)
__device__ float g_cur_rd[FLAT_ALL];        // cur_rd
__device__ float g_prop[2 * FLAT_ALL];      // D0 (d0;s0) then R0
__device__ float g_w[ERR_ + EDD_ + ERD_];   // normalized edge weights
__device__ float g_deg[2*N_DRUG + 2*N_DIS + 2*N_RDN];

// -------- threefry2x32 (bitwise identical to JAX) --------
__device__ __forceinline__ uint2 tf2x32(uint32_t k0, uint32_t k1, uint32_t x0, uint32_t x1) {
    uint32_t k2 = k0 ^ k1 ^ 0x1BD11BDAu;
#define TFR(r) x0 += x1; x1 = __funnelshift_l(x1, x1, r); x1 ^= x0;
    x0 += k0; x1 += k1;
    TFR(13) TFR(15) TFR(26) TFR(6)
    x0 += k1; x1 += k2 + 1u;
    TFR(17) TFR(29) TFR(16) TFR(24)
    x0 += k2; x1 += k0 + 2u;
    TFR(13) TFR(15) TFR(26) TFR(6)
    x0 += k0; x1 += k1 + 3u;
    TFR(17) TFR(29) TFR(16) TFR(24)
    x0 += k1; x1 += k2 + 4u;
    TFR(13) TFR(15) TFR(26) TFR(6)
    x0 += k2; x1 += k0 + 5u;
#undef TFR
    return make_uint2(x0, x1);
}

// partitionable counter-mode 32-bit random bits: threefry(key, (0, ctr)), xor halves
__device__ __forceinline__ uint32_t rbits32(uint32_t k0, uint32_t k1, uint32_t ctr) {
    uint2 o = tf2x32(k0, k1, 0u, ctr);
    return o.x ^ o.y;
}

__device__ __forceinline__ float u01(uint32_t b) {
    return __uint_as_float((b >> 9) | 0x3f800000u) - 1.0f;
}

__device__ __forceinline__ float wsum(float v) {
#pragma unroll
    for (int o = 16; o; o >>= 1) v += __shfl_xor_sync(0xffffffffu, v, o);
    return v;
}

// -------- kernels --------
__global__ void deg_kernel(const int* __restrict__ row, const int* __restrict__ col,
                           const float* __restrict__ val, int E,
                           float* __restrict__ dr, float* __restrict__ dc) {
    int e = blockIdx.x * blockDim.x + threadIdx.x;
    if (e >= E) return;
    float v = val[e];
    atomicAdd(&dr[row[e]], v);
    atomicAdd(&dc[col[e]], v);
}

__global__ void wgt_kernel(const int* __restrict__ row, const int* __restrict__ col,
                           const float* __restrict__ val, int E,
                           const float* __restrict__ dr, const float* __restrict__ dc,
                           float* __restrict__ w) {
    int e = blockIdx.x * blockDim.x + threadIdx.x;
    if (e >= E) return;
    w[e] = val[e] * rsqrtf(fmaxf(dr[row[e]] * dc[col[e]], 1e-12f));
}

// rr0 = emb * sigmoid(emb @ W + b); writes cur slot AND initializes drugE/disE accumulator.
__global__ void gate_kernel(const float* __restrict__ emb, const float* __restrict__ W,
                            const float* __restrict__ b, int N,
                            float* __restrict__ cur_out, float* __restrict__ acc_out) {
    __shared__ float Ws[HID * HID];
    __shared__ float bs[HID];
    for (int i = threadIdx.x; i < HID * HID; i += blockDim.x) Ws[i] = W[i];
    if (threadIdx.x < HID) bs[threadIdx.x] = b[threadIdx.x];
    __syncthreads();
    int gw = (blockIdx.x * blockDim.x + threadIdx.x) >> 5;
    int lane = threadIdx.x & 31;
    if (gw >= N) return;
    const float* er = emb + gw * HID;
    float e0 = er[lane], e1 = er[lane + 32];
    float a0 = 0.f, a1 = 0.f;
#pragma unroll 8
    for (int k = 0; k < 32; k++) {
        float ek = __shfl_sync(0xffffffffu, e0, k);
        a0 += ek * Ws[k * HID + lane];
        a1 += ek * Ws[k * HID + lane + 32];
    }
#pragma unroll 8
    for (int k = 0; k < 32; k++) {
        float ek = __shfl_sync(0xffffffffu, e1, k);
        a0 += ek * Ws[(k + 32) * HID + lane];
        a1 += ek * Ws[(k + 32) * HID + lane + 32];
    }
    float v0 = e0 / (1.0f + expf(-(a0 + bs[lane])));
    float v1 = e1 / (1.0f + expf(-(a1 + bs[lane + 32])));
    cur_out[gw * HID + lane]      = v0;
    cur_out[gw * HID + lane + 32] = v1;
    acc_out[gw * HID + lane]      = v0;
    acc_out[gw * HID + lane + 32] = v1;
}

// cur_rd = concat(drug, dis); rd_stack slot 0 = same
__global__ void init_copy(const float* __restrict__ drug, const float* __restrict__ dis,
                          float* __restrict__ cur_rd, float* __restrict__ out) {
    int idx = blockIdx.x * blockDim.x + threadIdx.x;
    if (idx >= FLAT_ALL) return;
    float e = (idx < FLAT_DRUG) ? drug[idx] : dis[idx - FLAT_DRUG];
    cur_rd[idx] = e;
    int n = idx >> 6, c = idx & 63;
    out[OFF_STACK + n * 256 + c] = e;
}

// edge-parallel SpMM scatter: 16 threads/edge, vector global reduction
__global__ void spmm_kernel(const int* __restrict__ row, const int* __restrict__ col,
                            const float* __restrict__ w, int E,
                            const float4* __restrict__ x, float* __restrict__ out) {
    int t = blockIdx.x * blockDim.x + threadIdx.x;
    int e = t >> 4;
    if (e >= E) return;
    int s = t & 15;
    int rr = __ldg(row + e), cc = __ldg(col + e);
    float wv = __ldg(w + e);
    float4 xv = __ldg(x + cc * 16 + s);
    float* dst = out + rr * 64 + s * 4;
    asm volatile("red.global.add.v4.f32 [%0], {%1, %2, %3, %4};"
                 :: "l"(dst), "f"(wv * xv.x), "f"(wv * xv.y), "f"(wv * xv.z), "f"(wv * xv.w)
                 : "memory");
}

// One warp per (drug row r, dis row r) pair: threefry noise, sign-noise add,
// l2n(r0)->rd_stack, l2n(d0)->drugE/disE accum, recurrence update.
__global__ void fuse_kernel(const float* __restrict__ D0, const float* __restrict__ R0,
                            float* __restrict__ cur_ds, float* __restrict__ cur_rd,
                            float* __restrict__ out, uint32_t k0, uint32_t k1, int slot) {
    int gw = (blockIdx.x * blockDim.x + threadIdx.x) >> 5;
    int lane = threadIdx.x & 31;
    if (gw >= N_DRUG) return;
    int r = gw;
    float nd[2], ns[2], r0d[2], r0s[2], d0v[2], s0v[2];
#pragma unroll
    for (int q = 0; q < 2; q++) {
        int c = lane + q * 32;
        int id = r * HID + c;            // flat index, drug half (== counter)
        int is = id + FLAT_DRUG;         // flat index, dis half (== counter)
        nd[q] = u01(rbits32(k0, k1, (uint32_t)id));
        ns[q] = u01(rbits32(k0, k1, (uint32_t)is));
        r0d[q] = R0[id]; r0s[q] = R0[is];
        d0v[q] = D0[id]; s0v[q] = D0[is];
    }
    float scnd  = 0.1f / fmaxf(sqrtf(wsum(nd[0]*nd[0] + nd[1]*nd[1])), 1e-12f);
    float scns  = 0.1f / fmaxf(sqrtf(wsum(ns[0]*ns[0] + ns[1]*ns[1])), 1e-12f);
    float invd0 = 1.0f / fmaxf(sqrtf(wsum(d0v[0]*d0v[0] + d0v[1]*d0v[1])), 1e-12f);
    float invs0 = 1.0f / fmaxf(sqrtf(wsum(s0v[0]*s0v[0] + s0v[1]*s0v[1])), 1e-12f);
    float rnewd[2], rnews[2];
#pragma unroll
    for (int q = 0; q < 2; q++) {
        float sgd = (r0d[q] > 0.f) ? 1.f : ((r0d[q] < 0.f) ? -1.f : 0.f);
        float sgs = (r0s[q] > 0.f) ? 1.f : ((r0s[q] < 0.f) ? -1.f : 0.f);
        rnewd[q] = r0d[q] + sgd * nd[q] * scnd;
        rnews[q] = r0s[q] + sgs * ns[q] * scns;
    }
    float invrd = 1.0f / fmaxf(sqrtf(wsum(rnewd[0]*rnewd[0] + rnewd[1]*rnewd[1])), 1e-12f);
    float invrs = 1.0f / fmaxf(sqrtf(wsum(rnews[0]*rnews[0] + rnews[1]*rnews[1])), 1e-12f);
#pragma unroll
    for (int q = 0; q < 2; q++) {
        int c = lane + q * 32;
        int id = r * HID + c;
        int is = id + FLAT_DRUG;
        out[OFF_STACK + r * 256 + slot * 64 + c] = rnewd[q] * invrd;
        out[OFF_STACK + (r + N_DRUG) * 256 + slot * 64 + c] = rnews[q] * invrs;
        out[OFF_DRUGE + id] += d0v[q] * invd0;
        out[OFF_DISE  + id] += s0v[q] * invs0;
        float cd = 0.5f * d0v[q] + 0.5f * rnewd[q];
        float cs = 0.5f * s0v[q] + 0.5f * rnews[q];
        cur_ds[id] = cd; cur_rd[id] = cd;
        cur_ds[is] = cs; cur_rd[is] = cs;
    }
}

// finalize: drugE/disE = acc/4; drugAll/disAll = 0.5*emb + 0.5*E; rd_drug/rd_dis = emb; meta = 0
__global__ void final_kernel(const float* __restrict__ drug, const float* __restrict__ dis,
                             float* __restrict__ out) {
    int idx = blockIdx.x * blockDim.x + threadIdx.x;
    if (idx >= FLAT_ALL) return;
    float e = (idx < FLAT_DRUG) ? drug[idx] : dis[idx - FLAT_DRUG];
    float Ev = out[idx] * 0.25f;
    out[idx] = Ev;
    out[OFF_ALL + idx] = 0.5f * e + 0.5f * Ev;
    out[OFF_RD + idx] = e;
    if (idx == 0) out[OFF_META] = 0.0f;
}

// -------- host threefry (per-layer keys via fold_in; unaffected by partitionable) --------
static inline void h_tf2x32(uint32_t k0, uint32_t k1, uint32_t x0, uint32_t x1,
                            uint32_t& o0, uint32_t& o1) {
    uint32_t k2 = k0 ^ k1 ^ 0x1BD11BDAu;
#define HROT(v, r) (((v) << (r)) | ((v) >> (32 - (r))))
#define HTFR(r) { x0 += x1; x1 = HROT(x1, r); x1 ^= x0; }
    x0 += k0; x1 += k1;
    HTFR(13) HTFR(15) HTFR(26) HTFR(6)
    x0 += k1; x1 += k2 + 1u;
    HTFR(17) HTFR(29) HTFR(16) HTFR(24)
    x0 += k2; x1 += k0 + 2u;
    HTFR(13) HTFR(15) HTFR(26) HTFR(6)
    x0 += k0; x1 += k1 + 3u;
    HTFR(17) HTFR(29) HTFR(16) HTFR(24)
    x0 += k1; x1 += k2 + 4u;
    HTFR(13) HTFR(15) HTFR(26) HTFR(6)
    x0 += k2; x1 += k0 + 5u;
#undef HTFR
#undef HROT
    o0 = x0; o1 = x1;
}

extern "C" void kernel_launch(void* const* d_in, const int* in_sizes, int n_in,
                              void* d_out, int out_size) {
    const float* drug_emb = (const float*)d_in[0];
    const float* dis_emb  = (const float*)d_in[1];
    const float* Wr = (const float*)d_in[2];
    const float* br = (const float*)d_in[3];
    const float* Wd = (const float*)d_in[4];
    const float* bd = (const float*)d_in[5];
    const int*   rr_row = (const int*)d_in[6];
    const int*   rr_col = (const int*)d_in[7];
    const float* rr_val = (const float*)d_in[8];
    const int*   dd_row = (const int*)d_in[9];
    const int*   dd_col = (const int*)d_in[10];
    const float* dd_val = (const float*)d_in[11];
    const int*   rd_row = (const int*)d_in[12];
    const int*   rd_col = (const int*)d_in[13];
    const float* rd_val = (const float*)d_in[14];
    float* out = (float*)d_out;

    float *cur_ds, *cur_rd, *prop, *w, *deg;
    cudaGetSymbolAddress((void**)&cur_ds, g_cur_ds);
    cudaGetSymbolAddress((void**)&cur_rd, g_cur_rd);
    cudaGetSymbolAddress((void**)&prop,   g_prop);
    cudaGetSymbolAddress((void**)&w,      g_w);
    cudaGetSymbolAddress((void**)&deg,    g_deg);

    float* wrr = w;
    float* wdd = w + ERR_;
    float* wrd = w + ERR_ + EDD_;
    float* rr_dr = deg;
    float* rr_dc = deg + N_DRUG;
    float* dd_dr = deg + 2 * N_DRUG;
    float* dd_dc = deg + 2 * N_DRUG + N_DIS;
    float* rd_dr = deg + 2 * N_DRUG + 2 * N_DIS;
    float* rd_dc = deg + 2 * N_DRUG + 2 * N_DIS + N_RDN;

    const int B = 256;

    // degrees + weights (constant per launch)
    cudaMemsetAsync(deg, 0, sizeof(float) * (2 * N_DRUG + 2 * N_DIS + 2 * N_RDN), 0);
    deg_kernel<<<(ERR_ + B - 1) / B, B>>>(rr_row, rr_col, rr_val, ERR_, rr_dr, rr_dc);
    deg_kernel<<<(EDD_ + B - 1) / B, B>>>(dd_row, dd_col, dd_val, EDD_, dd_dr, dd_dc);
    deg_kernel<<<(ERD_ + B - 1) / B, B>>>(rd_row, rd_col, rd_val, ERD_, rd_dr, rd_dc);
    wgt_kernel<<<(ERR_ + B - 1) / B, B>>>(rr_row, rr_col, rr_val, ERR_, rr_dr, rr_dc, wrr);
    wgt_kernel<<<(EDD_ + B - 1) / B, B>>>(dd_row, dd_col, dd_val, EDD_, dd_dr, dd_dc, wdd);
    wgt_kernel<<<(ERD_ + B - 1) / B, B>>>(rd_row, rd_col, rd_val, ERD_, rd_dr, rd_dc, wrd);

    // init: rr0/dd0 into cur_ds and drugE/disE accumulators; cur_rd = concat(emb); stack slot 0
    gate_kernel<<<(N_DRUG * 32) / B, B>>>(drug_emb, Wr, br, N_DRUG, cur_ds, out + OFF_DRUGE);
    gate_kernel<<<(N_DIS * 32) / B, B>>>(dis_emb, Wd, bd, N_DIS, cur_ds + FLAT_DRUG, out + OFF_DISE);
    init_copy<<<(FLAT_ALL + B - 1) / B, B>>>(drug_emb, dis_emb, cur_rd, out);

    for (int i = 0; i < 3; i++) {
        uint32_t kk0, kk1;
        h_tf2x32(0u, 1u, 0u, (uint32_t)i, kk0, kk1);  // fold_in(key(1), i)

        cudaMemsetAsync(prop, 0, sizeof(float) * 2 * FLAT_ALL, 0);
        spmm_kernel<<<(ERR_ * 16 + B - 1) / B, B>>>(rr_row, rr_col, wrr, ERR_,
                                                    (const float4*)cur_ds, prop);
        spmm_kernel<<<(EDD_ * 16 + B - 1) / B, B>>>(dd_row, dd_col, wdd, EDD_,
                                                    (const float4*)(cur_ds + FLAT_DRUG),
                                                    prop + FLAT_DRUG);
        spmm_kernel<<<(ERD_ * 16 + B - 1) / B, B>>>(rd_row, rd_col, wrd, ERD_,
                                                    (const float4*)cur_rd, prop + FLAT_ALL);
        fuse_kernel<<<(N_DRUG * 32) / B, B>>>(prop, prop + FLAT_ALL, cur_ds, cur_rd,
                                              out, kk0, kk1, i + 1);
    }

    final_kernel<<<(FLAT_ALL + B - 1) / B, B>>>(drug_emb, dis_emb, out);
}

// round 6
// speedup vs baseline: 1.5640x; 1.5640x over previous
#include <cuda_runtime.h>
#include <cstdint>

#define N_DRUG 100000
#define N_DIS  100000
#define N_RDN  200000
#define HID    64
#define ERR_   1600000
#define EDD_   1600000
#define ERD_   3200000
#define E_TOT  6400000
#define NROWS  400000      // rr rows (100k) + dd rows (100k) + rd rows (200k)
#define FLAT_DRUG 6400000
#define FLAT_ALL  12800000

// d_out layout (float32):
#define OFF_DRUGE  0
#define OFF_DISE   6400000
#define OFF_ALL    12800000
#define OFF_RD     25600000
#define OFF_META   38400000
#define OFF_STACK  38400001   // rd_stack [200000,4,64]

#define NBLK1 ((NROWS + 1023) / 1024)   // 391

// -------- scratch (static device globals) --------
__device__ float g_cur_ds[FLAT_ALL];
__device__ float g_cur_rd[FLAT_ALL];        // only needed for layer-0 rd source
__device__ float g_prop[2 * FLAT_ALL];      // D0 (d0;s0) then R0
__device__ float g_deg[2*N_DRUG + 2*N_DIS + 2*N_RDN];
__device__ int   g_cnt[NROWS];
__device__ int   g_cursor[NROWS];
__device__ int   g_rowptr[NROWS + 1];
__device__ int   g_bsum[512];
__device__ int   g_cols[E_TOT];
__device__ float g_ws[E_TOT];

// -------- threefry2x32 (bitwise identical to JAX) --------
__device__ __forceinline__ uint2 tf2x32(uint32_t k0, uint32_t k1, uint32_t x0, uint32_t x1) {
    uint32_t k2 = k0 ^ k1 ^ 0x1BD11BDAu;
#define TFR(r) x0 += x1; x1 = __funnelshift_l(x1, x1, r); x1 ^= x0;
    x0 += k0; x1 += k1;
    TFR(13) TFR(15) TFR(26) TFR(6)
    x0 += k1; x1 += k2 + 1u;
    TFR(17) TFR(29) TFR(16) TFR(24)
    x0 += k2; x1 += k0 + 2u;
    TFR(13) TFR(15) TFR(26) TFR(6)
    x0 += k0; x1 += k1 + 3u;
    TFR(17) TFR(29) TFR(16) TFR(24)
    x0 += k1; x1 += k2 + 4u;
    TFR(13) TFR(15) TFR(26) TFR(6)
    x0 += k2; x1 += k0 + 5u;
#undef TFR
    return make_uint2(x0, x1);
}

// partitionable counter-mode 32-bit random bits: threefry(key, (0, ctr)), xor halves
__device__ __forceinline__ uint32_t rbits32(uint32_t k0, uint32_t k1, uint32_t ctr) {
    uint2 o = tf2x32(k0, k1, 0u, ctr);
    return o.x ^ o.y;
}

__device__ __forceinline__ float u01(uint32_t b) {
    return __uint_as_float((b >> 9) | 0x3f800000u) - 1.0f;
}

__device__ __forceinline__ float wsum(float v) {
#pragma unroll
    for (int o = 16; o; o >>= 1) v += __shfl_xor_sync(0xffffffffu, v, o);
    return v;
}

// -------- CSR build --------
// degrees + row counts in one pass
__global__ void deg_cnt_kernel(const int* __restrict__ row, const int* __restrict__ col,
                               const float* __restrict__ val, int E,
                               float* __restrict__ dr, float* __restrict__ dc,
                               int* __restrict__ cnt) {
    int e = blockIdx.x * blockDim.x + threadIdx.x;
    if (e >= E) return;
    float v = val[e];
    int r = row[e];
    atomicAdd(&dr[r], v);
    atomicAdd(&dc[col[e]], v);
    atomicAdd(&cnt[r], 1);
}

// block-wise inclusive scan of counts -> rowptr[i+1]; block sums out
__global__ void scan1_kernel(const int* __restrict__ cnt, int* __restrict__ rowptr,
                             int* __restrict__ bsum) {
    __shared__ int s[1024];
    int i = blockIdx.x * 1024 + threadIdx.x;
    int v = (i < NROWS) ? cnt[i] : 0;
    s[threadIdx.x] = v;
    __syncthreads();
#pragma unroll
    for (int o = 1; o < 1024; o <<= 1) {
        int t = (threadIdx.x >= o) ? s[threadIdx.x - o] : 0;
        __syncthreads();
        s[threadIdx.x] += t;
        __syncthreads();
    }
    if (i < NROWS) rowptr[i + 1] = s[threadIdx.x];
    if (threadIdx.x == 1023) bsum[blockIdx.x] = s[1023];
}

// exclusive scan of block sums (single block, nb <= 512)
__global__ void scan2_kernel(int* __restrict__ bsum, int nb) {
    __shared__ int s[512];
    int v = (threadIdx.x < nb) ? bsum[threadIdx.x] : 0;
    s[threadIdx.x] = v;
    __syncthreads();
#pragma unroll
    for (int o = 1; o < 512; o <<= 1) {
        int t = (threadIdx.x >= o) ? s[threadIdx.x - o] : 0;
        __syncthreads();
        s[threadIdx.x] += t;
        __syncthreads();
    }
    if (threadIdx.x < nb) bsum[threadIdx.x] = (threadIdx.x == 0) ? 0 : s[threadIdx.x - 1];
}

// add block offsets; set rowptr[0]=0
__global__ void scan3_kernel(int* __restrict__ rowptr, const int* __restrict__ bsum) {
    int i = blockIdx.x * 1024 + threadIdx.x;
    if (i < NROWS) rowptr[i + 1] += bsum[blockIdx.x];
    if (i == 0) rowptr[0] = 0;
}

// scatter edges into CSR buckets with normalized weight fused in
__global__ void fill_kernel(const int* __restrict__ row, const int* __restrict__ col,
                            const float* __restrict__ val, int E,
                            const float* __restrict__ dr, const float* __restrict__ dc,
                            const int* __restrict__ rowptr, int* __restrict__ cursor,
                            int* __restrict__ cols, float* __restrict__ ws) {
    int e = blockIdx.x * blockDim.x + threadIdx.x;
    if (e >= E) return;
    int r = row[e], c = col[e];
    int pos = atomicAdd(&cursor[r], 1);
    int idx = rowptr[r] + pos;
    cols[idx] = c;
    ws[idx] = val[e] * rsqrtf(fmaxf(dr[r] * dc[c], 1e-12f));
}

// -------- init --------
__global__ void gate_kernel(const float* __restrict__ emb, const float* __restrict__ W,
                            const float* __restrict__ b, int N,
                            float* __restrict__ cur_out, float* __restrict__ acc_out) {
    __shared__ float Ws[HID * HID];
    __shared__ float bs[HID];
    for (int i = threadIdx.x; i < HID * HID; i += blockDim.x) Ws[i] = W[i];
    if (threadIdx.x < HID) bs[threadIdx.x] = b[threadIdx.x];
    __syncthreads();
    int gw = (blockIdx.x * blockDim.x + threadIdx.x) >> 5;
    int lane = threadIdx.x & 31;
    if (gw >= N) return;
    const float* er = emb + gw * HID;
    float e0 = er[lane], e1 = er[lane + 32];
    float a0 = 0.f, a1 = 0.f;
#pragma unroll 8
    for (int k = 0; k < 32; k++) {
        float ek = __shfl_sync(0xffffffffu, e0, k);
        a0 += ek * Ws[k * HID + lane];
        a1 += ek * Ws[k * HID + lane + 32];
    }
#pragma unroll 8
    for (int k = 0; k < 32; k++) {
        float ek = __shfl_sync(0xffffffffu, e1, k);
        a0 += ek * Ws[(k + 32) * HID + lane];
        a1 += ek * Ws[(k + 32) * HID + lane + 32];
    }
    float v0 = e0 / (1.0f + expf(-(a0 + bs[lane])));
    float v1 = e1 / (1.0f + expf(-(a1 + bs[lane + 32])));
    cur_out[gw * HID + lane]      = v0;
    cur_out[gw * HID + lane + 32] = v1;
    acc_out[gw * HID + lane]      = v0;
    acc_out[gw * HID + lane + 32] = v1;
}

__global__ void init_copy(const float* __restrict__ drug, const float* __restrict__ dis,
                          float* __restrict__ cur_rd, float* __restrict__ out) {
    int idx = blockIdx.x * blockDim.x + threadIdx.x;
    if (idx >= FLAT_ALL) return;
    float e = (idx < FLAT_DRUG) ? drug[idx] : dis[idx - FLAT_DRUG];
    cur_rd[idx] = e;
    int n = idx >> 6, c = idx & 63;
    out[OFF_STACK + n * 256 + c] = e;
}

// -------- gather SpMM: one warp per CSR row over all three graphs --------
// rows [0,100k): rr graph, x=cur_ds(drug half), dst=prop D0 drug
// rows [100k,200k): dd graph, x=cur_ds dis half, dst=prop D0 dis
// rows [200k,400k): rd graph, x=rd_src, dst=prop R0
__global__ void spmm_gather(const int* __restrict__ rowptr,
                            const int* __restrict__ cols,
                            const float* __restrict__ ws,
                            const float* __restrict__ xds,
                            const float* __restrict__ xrd,
                            float* __restrict__ prop) {
    int u = (blockIdx.x * blockDim.x + threadIdx.x) >> 5;
    int lane = threadIdx.x & 31;
    if (u >= NROWS) return;
    int start = __ldg(rowptr + u), end = __ldg(rowptr + u + 1);
    const float2* x2;
    float2* dst;
    if (u < N_DRUG) {
        x2 = (const float2*)xds;
        dst = (float2*)prop + (size_t)u * 32;
    } else if (u < N_DRUG + N_DIS) {
        x2 = (const float2*)(xds + FLAT_DRUG);
        dst = (float2*)prop + (size_t)u * 32;   // dis rows are contiguous after drug rows
    } else {
        x2 = (const float2*)xrd;
        dst = (float2*)(prop + FLAT_ALL) + (size_t)(u - N_DRUG - N_DIS) * 32;
    }
    float a0 = 0.f, a1 = 0.f;
    int j = start;
    for (; j + 2 <= end; j += 2) {
        int c0 = __ldg(cols + j), c1 = __ldg(cols + j + 1);
        float w0 = __ldg(ws + j), w1 = __ldg(ws + j + 1);
        float2 v0 = __ldg(x2 + (size_t)c0 * 32 + lane);
        float2 v1 = __ldg(x2 + (size_t)c1 * 32 + lane);
        a0 += w0 * v0.x + w1 * v1.x;
        a1 += w0 * v0.y + w1 * v1.y;
    }
    if (j < end) {
        int c = __ldg(cols + j);
        float w = __ldg(ws + j);
        float2 v = __ldg(x2 + (size_t)c * 32 + lane);
        a0 += w * v.x;
        a1 += w * v.y;
    }
    dst[lane] = make_float2(a0, a1);
}

// -------- fused noise/l2n/recurrence: one warp per (drug r, dis r) pair --------
__global__ void fuse_kernel(const float* __restrict__ D0, const float* __restrict__ R0,
                            float* __restrict__ cur_ds,
                            float* __restrict__ out, uint32_t k0, uint32_t k1, int slot) {
    int gw = (blockIdx.x * blockDim.x + threadIdx.x) >> 5;
    int lane = threadIdx.x & 31;
    if (gw >= N_DRUG) return;
    int r = gw;
    float nd[2], ns[2], r0d[2], r0s[2], d0v[2], s0v[2];
#pragma unroll
    for (int q = 0; q < 2; q++) {
        int c = lane + q * 32;
        int id = r * HID + c;
        int is = id + FLAT_DRUG;
        nd[q] = u01(rbits32(k0, k1, (uint32_t)id));
        ns[q] = u01(rbits32(k0, k1, (uint32_t)is));
        r0d[q] = R0[id]; r0s[q] = R0[is];
        d0v[q] = D0[id]; s0v[q] = D0[is];
    }
    float scnd  = 0.1f / fmaxf(sqrtf(wsum(nd[0]*nd[0] + nd[1]*nd[1])), 1e-12f);
    float scns  = 0.1f / fmaxf(sqrtf(wsum(ns[0]*ns[0] + ns[1]*ns[1])), 1e-12f);
    float invd0 = 1.0f / fmaxf(sqrtf(wsum(d0v[0]*d0v[0] + d0v[1]*d0v[1])), 1e-12f);
    float invs0 = 1.0f / fmaxf(sqrtf(wsum(s0v[0]*s0v[0] + s0v[1]*s0v[1])), 1e-12f);
    float rnewd[2], rnews[2];
#pragma unroll
    for (int q = 0; q < 2; q++) {
        float sgd = (r0d[q] > 0.f) ? 1.f : ((r0d[q] < 0.f) ? -1.f : 0.f);
        float sgs = (r0s[q] > 0.f) ? 1.f : ((r0s[q] < 0.f) ? -1.f : 0.f);
        rnewd[q] = r0d[q] + sgd * nd[q] * scnd;
        rnews[q] = r0s[q] + sgs * ns[q] * scns;
    }
    float invrd = 1.0f / fmaxf(sqrtf(wsum(rnewd[0]*rnewd[0] + rnewd[1]*rnewd[1])), 1e-12f);
    float invrs = 1.0f / fmaxf(sqrtf(wsum(rnews[0]*rnews[0] + rnews[1]*rnews[1])), 1e-12f);
#pragma unroll
    for (int q = 0; q < 2; q++) {
        int c = lane + q * 32;
        int id = r * HID + c;
        int is = id + FLAT_DRUG;
        out[OFF_STACK + r * 256 + slot * 64 + c] = rnewd[q] * invrd;
        out[OFF_STACK + (r + N_DRUG) * 256 + slot * 64 + c] = rnews[q] * invrs;
        out[OFF_DRUGE + id] += d0v[q] * invd0;
        out[OFF_DISE  + id] += s0v[q] * invs0;
        cur_ds[id] = 0.5f * d0v[q] + 0.5f * rnewd[q];
        cur_ds[is] = 0.5f * s0v[q] + 0.5f * rnews[q];
    }
}

__global__ void final_kernel(const float* __restrict__ drug, const float* __restrict__ dis,
                             float* __restrict__ out) {
    int idx = blockIdx.x * blockDim.x + threadIdx.x;
    if (idx >= FLAT_ALL) return;
    float e = (idx < FLAT_DRUG) ? drug[idx] : dis[idx - FLAT_DRUG];
    float Ev = out[idx] * 0.25f;
    out[idx] = Ev;
    out[OFF_ALL + idx] = 0.5f * e + 0.5f * Ev;
    out[OFF_RD + idx] = e;
    if (idx == 0) out[OFF_META] = 0.0f;
}

// -------- host threefry (fold_in key derivation) --------
static inline void h_tf2x32(uint32_t k0, uint32_t k1, uint32_t x0, uint32_t x1,
                            uint32_t& o0, uint32_t& o1) {
    uint32_t k2 = k0 ^ k1 ^ 0x1BD11BDAu;
#define HROT(v, r) (((v) << (r)) | ((v) >> (32 - (r))))
#define HTFR(r) { x0 += x1; x1 = HROT(x1, r); x1 ^= x0; }
    x0 += k0; x1 += k1;
    HTFR(13) HTFR(15) HTFR(26) HTFR(6)
    x0 += k1; x1 += k2 + 1u;
    HTFR(17) HTFR(29) HTFR(16) HTFR(24)
    x0 += k2; x1 += k0 + 2u;
    HTFR(13) HTFR(15) HTFR(26) HTFR(6)
    x0 += k0; x1 += k1 + 3u;
    HTFR(17) HTFR(29) HTFR(16) HTFR(24)
    x0 += k1; x1 += k2 + 4u;
    HTFR(13) HTFR(15) HTFR(26) HTFR(6)
    x0 += k2; x1 += k0 + 5u;
#undef HTFR
#undef HROT
    o0 = x0; o1 = x1;
}

extern "C" void kernel_launch(void* const* d_in, const int* in_sizes, int n_in,
                              void* d_out, int out_size) {
    const float* drug_emb = (const float*)d_in[0];
    const float* dis_emb  = (const float*)d_in[1];
    const float* Wr = (const float*)d_in[2];
    const float* br = (const float*)d_in[3];
    const float* Wd = (const float*)d_in[4];
    const float* bd = (const float*)d_in[5];
    const int*   rr_row = (const int*)d_in[6];
    const int*   rr_col = (const int*)d_in[7];
    const float* rr_val = (const float*)d_in[8];
    const int*   dd_row = (const int*)d_in[9];
    const int*   dd_col = (const int*)d_in[10];
    const float* dd_val = (const float*)d_in[11];
    const int*   rd_row = (const int*)d_in[12];
    const int*   rd_col = (const int*)d_in[13];
    const float* rd_val = (const float*)d_in[14];
    float* out = (float*)d_out;

    float *cur_ds, *cur_rd, *prop, *deg, *ws;
    int *cnt, *cursor, *rowptr, *bsum, *cols;
    cudaGetSymbolAddress((void**)&cur_ds, g_cur_ds);
    cudaGetSymbolAddress((void**)&cur_rd, g_cur_rd);
    cudaGetSymbolAddress((void**)&prop,   g_prop);
    cudaGetSymbolAddress((void**)&deg,    g_deg);
    cudaGetSymbolAddress((void**)&cnt,    g_cnt);
    cudaGetSymbolAddress((void**)&cursor, g_cursor);
    cudaGetSymbolAddress((void**)&rowptr, g_rowptr);
    cudaGetSymbolAddress((void**)&bsum,   g_bsum);
    cudaGetSymbolAddress((void**)&cols,   g_cols);
    cudaGetSymbolAddress((void**)&ws,     g_ws);

    float* rr_dr = deg;
    float* rr_dc = deg + N_DRUG;
    float* dd_dr = deg + 2 * N_DRUG;
    float* dd_dc = deg + 2 * N_DRUG + N_DIS;
    float* rd_dr = deg + 2 * N_DRUG + 2 * N_DIS;
    float* rd_dc = deg + 2 * N_DRUG + 2 * N_DIS + N_RDN;

    const int B = 256;

    // ---- CSR build (per launch; deterministic work) ----
    cudaMemsetAsync(deg, 0, sizeof(float) * (2*N_DRUG + 2*N_DIS + 2*N_RDN), 0);
    cudaMemsetAsync(cnt, 0, sizeof(int) * NROWS, 0);
    cudaMemsetAsync(cursor, 0, sizeof(int) * NROWS, 0);

    deg_cnt_kernel<<<(ERR_ + B - 1) / B, B>>>(rr_row, rr_col, rr_val, ERR_, rr_dr, rr_dc, cnt);
    deg_cnt_kernel<<<(EDD_ + B - 1) / B, B>>>(dd_row, dd_col, dd_val, EDD_, dd_dr, dd_dc, cnt + N_DRUG);
    deg_cnt_kernel<<<(ERD_ + B - 1) / B, B>>>(rd_row, rd_col, rd_val, ERD_, rd_dr, rd_dc, cnt + N_DRUG + N_DIS);

    scan1_kernel<<<NBLK1, 1024>>>(cnt, rowptr, bsum);
    scan2_kernel<<<1, 512>>>(bsum, NBLK1);
    scan3_kernel<<<NBLK1, 1024>>>(rowptr, bsum);

    fill_kernel<<<(ERR_ + B - 1) / B, B>>>(rr_row, rr_col, rr_val, ERR_, rr_dr, rr_dc,
                                           rowptr, cursor, cols, ws);
    fill_kernel<<<(EDD_ + B - 1) / B, B>>>(dd_row, dd_col, dd_val, EDD_, dd_dr, dd_dc,
                                           rowptr + N_DRUG, cursor + N_DRUG, cols, ws);
    fill_kernel<<<(ERD_ + B - 1) / B, B>>>(rd_row, rd_col, rd_val, ERD_, rd_dr, rd_dc,
                                           rowptr + N_DRUG + N_DIS, cursor + N_DRUG + N_DIS,
                                           cols, ws);

    // ---- init ----
    gate_kernel<<<(N_DRUG * 32) / B, B>>>(drug_emb, Wr, br, N_DRUG, cur_ds, out + OFF_DRUGE);
    gate_kernel<<<(N_DIS * 32) / B, B>>>(dis_emb, Wd, bd, N_DIS, cur_ds + FLAT_DRUG, out + OFF_DISE);
    init_copy<<<(FLAT_ALL + B - 1) / B, B>>>(drug_emb, dis_emb, cur_rd, out);

    // ---- layers ----
    for (int i = 0; i < 3; i++) {
        uint32_t kk0, kk1;
        h_tf2x32(0u, 1u, 0u, (uint32_t)i, kk0, kk1);  // fold_in(key(1), i)

        const float* rd_src = (i == 0) ? cur_rd : cur_ds;  // cur_rd == cur_ds after layer 0
        spmm_gather<<<(NROWS * 32 + B - 1) / B, B>>>(rowptr, cols, ws, cur_ds, rd_src, prop);
        fuse_kernel<<<(N_DRUG * 32) / B, B>>>(prop, prop + FLAT_ALL, cur_ds,
                                              out, kk0, kk1, i + 1);
    }

    final_kernel<<<(FLAT_ALL + B - 1) / B, B>>>(drug_emb, dis_emb, out);
}

// round 11
// speedup vs baseline: 1.5789x; 1.0096x over previous
#include <cuda_runtime.h>
#include <cstdint>

#define N_DRUG 100000
#define N_DIS  100000
#define N_RDN  200000
#define HID    64
#define ERR_   1600000
#define EDD_   1600000
#define ERD_   3200000
#define E_TOT  6400000
#define NROWS  400000      // rr rows [0,100k) + dd rows [100k,200k) + rd rows [200k,400k)
#define FLAT_DRUG 6400000
#define FLAT_ALL  12800000

// d_out layout (float32):
#define OFF_DRUGE  0
#define OFF_DISE   6400000
#define OFF_ALL    12800000
#define OFF_RD     25600000
#define OFF_META   38400000
#define OFF_STACK  38400001   // rd_stack [200000,4,64]  -- ODD offset: scalar stores only!

#define NBLK1 ((NROWS + 1023) / 1024)   // 391

// -------- scratch (static device globals) --------
__device__ float g_cur0[FLAT_ALL];          // ping
__device__ float g_cur1[FLAT_ALL];          // pong
__device__ float g_deg[2*N_DRUG + 2*N_DIS + 2*N_RDN];
__device__ int   g_cnt[NROWS];
__device__ int   g_cursor[NROWS];           // absolute write cursors (init from rowptr)
__device__ int   g_rowptr[NROWS + 1];
__device__ int   g_bsum[512];
__device__ int   g_cols[E_TOT];
__device__ float g_ws[E_TOT];

// -------- threefry2x32 (bitwise identical to JAX) --------
__device__ __forceinline__ uint2 tf2x32(uint32_t k0, uint32_t k1, uint32_t x0, uint32_t x1) {
    uint32_t k2 = k0 ^ k1 ^ 0x1BD11BDAu;
#define TFR(r) x0 += x1; x1 = __funnelshift_l(x1, x1, r); x1 ^= x0;
    x0 += k0; x1 += k1;
    TFR(13) TFR(15) TFR(26) TFR(6)
    x0 += k1; x1 += k2 + 1u;
    TFR(17) TFR(29) TFR(16) TFR(24)
    x0 += k2; x1 += k0 + 2u;
    TFR(13) TFR(15) TFR(26) TFR(6)
    x0 += k0; x1 += k1 + 3u;
    TFR(17) TFR(29) TFR(16) TFR(24)
    x0 += k1; x1 += k2 + 4u;
    TFR(13) TFR(15) TFR(26) TFR(6)
    x0 += k2; x1 += k0 + 5u;
#undef TFR
    return make_uint2(x0, x1);
}

// partitionable counter-mode 32-bit random bits: threefry(key, (0, ctr)), xor halves
__device__ __forceinline__ uint32_t rbits32(uint32_t k0, uint32_t k1, uint32_t ctr) {
    uint2 o = tf2x32(k0, k1, 0u, ctr);
    return o.x ^ o.y;
}

__device__ __forceinline__ float u01(uint32_t b) {
    return __uint_as_float((b >> 9) | 0x3f800000u) - 1.0f;
}

__device__ __forceinline__ float wsum(float v) {
#pragma unroll
    for (int o = 16; o; o >>= 1) v += __shfl_xor_sync(0xffffffffu, v, o);
    return v;
}

__device__ __forceinline__ float sgnf(float v) {
    return (v > 0.f) ? 1.f : ((v < 0.f) ? -1.f : 0.f);
}

// -------- CSR build --------
__global__ void deg_cnt_kernel(const int* __restrict__ row, const int* __restrict__ col,
                               const float* __restrict__ val, int E,
                               float* __restrict__ dr, float* __restrict__ dc,
                               int* __restrict__ cnt) {
    int e = blockIdx.x * blockDim.x + threadIdx.x;
    if (e >= E) return;
    float v = val[e];
    int r = row[e];
    atomicAdd(&dr[r], v);
    atomicAdd(&dc[col[e]], v);
    atomicAdd(&cnt[r], 1);
}

__global__ void scan1_kernel(const int* __restrict__ cnt, int* __restrict__ rowptr,
                             int* __restrict__ bsum) {
    __shared__ int s[1024];
    int i = blockIdx.x * 1024 + threadIdx.x;
    int v = (i < NROWS) ? cnt[i] : 0;
    s[threadIdx.x] = v;
    __syncthreads();
#pragma unroll
    for (int o = 1; o < 1024; o <<= 1) {
        int t = (threadIdx.x >= o) ? s[threadIdx.x - o] : 0;
        __syncthreads();
        s[threadIdx.x] += t;
        __syncthreads();
    }
    if (i < NROWS) rowptr[i + 1] = s[threadIdx.x];
    if (threadIdx.x == 1023) bsum[blockIdx.x] = s[1023];
}

__global__ void scan2_kernel(int* __restrict__ bsum, int nb) {
    __shared__ int s[512];
    int v = (threadIdx.x < nb) ? bsum[threadIdx.x] : 0;
    s[threadIdx.x] = v;
    __syncthreads();
#pragma unroll
    for (int o = 1; o < 512; o <<= 1) {
        int t = (threadIdx.x >= o) ? s[threadIdx.x - o] : 0;
        __syncthreads();
        s[threadIdx.x] += t;
        __syncthreads();
    }
    if (threadIdx.x < nb) bsum[threadIdx.x] = (threadIdx.x == 0) ? 0 : s[threadIdx.x - 1];
}

__global__ void scan3_kernel(int* __restrict__ rowptr, const int* __restrict__ bsum) {
    int i = blockIdx.x * 1024 + threadIdx.x;
    if (i < NROWS) rowptr[i + 1] += bsum[blockIdx.x];
    if (i == 0) rowptr[0] = 0;
}

// cursor[i] = rowptr[i]  (absolute cursors, drop memset + rowptr read in fill)
__global__ void cursor_init_kernel(const int* __restrict__ rowptr, int* __restrict__ cursor) {
    int i = blockIdx.x * blockDim.x + threadIdx.x;
    if (i < NROWS) cursor[i] = rowptr[i];
}

__global__ void fill_kernel(const int* __restrict__ row, const int* __restrict__ col,
                            const float* __restrict__ val, int E,
                            const float* __restrict__ dr, const float* __restrict__ dc,
                            int* __restrict__ cursor,
                            int* __restrict__ cols, float* __restrict__ ws) {
    int e = blockIdx.x * blockDim.x + threadIdx.x;
    if (e >= E) return;
    int r = row[e], c = col[e];
    int idx = atomicAdd(&cursor[r], 1);
    cols[idx] = c;
    ws[idx] = val[e] * rsqrtf(fmaxf(dr[r] * dc[c], 1e-12f));
}

// -------- init: gate + drugE/disE accumulator init + stack slot-0 write --------
__global__ void gate_kernel(const float* __restrict__ emb, const float* __restrict__ W,
                            const float* __restrict__ b, int N,
                            float* __restrict__ cur_out, float* __restrict__ acc_out,
                            float* __restrict__ stack_base) {  // out+OFF_STACK (+100k rows for dis)
    __shared__ float Ws[HID * HID];
    __shared__ float bs[HID];
    for (int i = threadIdx.x; i < HID * HID; i += blockDim.x) Ws[i] = W[i];
    if (threadIdx.x < HID) bs[threadIdx.x] = b[threadIdx.x];
    __syncthreads();
    int gw = (blockIdx.x * blockDim.x + threadIdx.x) >> 5;
    int lane = threadIdx.x & 31;
    if (gw >= N) return;
    const float* er = emb + gw * HID;
    float e0 = er[lane], e1 = er[lane + 32];
    float a0 = 0.f, a1 = 0.f;
#pragma unroll 8
    for (int k = 0; k < 32; k++) {
        float ek = __shfl_sync(0xffffffffu, e0, k);
        a0 += ek * Ws[k * HID + lane];
        a1 += ek * Ws[k * HID + lane + 32];
    }
#pragma unroll 8
    for (int k = 0; k < 32; k++) {
        float ek = __shfl_sync(0xffffffffu, e1, k);
        a0 += ek * Ws[(k + 32) * HID + lane];
        a1 += ek * Ws[(k + 32) * HID + lane + 32];
    }
    float v0 = e0 / (1.0f + expf(-(a0 + bs[lane])));
    float v1 = e1 / (1.0f + expf(-(a1 + bs[lane + 32])));
    cur_out[gw * HID + lane]      = v0;
    cur_out[gw * HID + lane + 32] = v1;
    acc_out[gw * HID + lane]      = v0;
    acc_out[gw * HID + lane + 32] = v1;
    stack_base[gw * 256 + lane]      = e0;   // slot 0 = raw embedding
    stack_base[gw * 256 + lane + 32] = e1;
}

// -------- gather one CSR row (float2 per lane), 4-edge unroll --------
// column c selects xa (c < N_DRUG) or xb (c - N_DRUG)
__device__ __forceinline__ float2 gather_row(const int* __restrict__ cols,
                                             const float* __restrict__ ws,
                                             int start, int end, int lane,
                                             const float2* __restrict__ xa,
                                             const float2* __restrict__ xb) {
    float a0 = 0.f, a1 = 0.f;
    int j = start;
    for (; j + 4 <= end; j += 4) {
        int c0 = __ldg(cols + j),     c1 = __ldg(cols + j + 1);
        int c2 = __ldg(cols + j + 2), c3 = __ldg(cols + j + 3);
        float w0 = __ldg(ws + j),     w1 = __ldg(ws + j + 1);
        float w2 = __ldg(ws + j + 2), w3 = __ldg(ws + j + 3);
        const float2* p0 = (c0 < N_DRUG) ? xa + (size_t)c0 * 32 : xb + (size_t)(c0 - N_DRUG) * 32;
        const float2* p1 = (c1 < N_DRUG) ? xa + (size_t)c1 * 32 : xb + (size_t)(c1 - N_DRUG) * 32;
        const float2* p2 = (c2 < N_DRUG) ? xa + (size_t)c2 * 32 : xb + (size_t)(c2 - N_DRUG) * 32;
        const float2* p3 = (c3 < N_DRUG) ? xa + (size_t)c3 * 32 : xb + (size_t)(c3 - N_DRUG) * 32;
        float2 v0 = __ldg(p0 + lane), v1 = __ldg(p1 + lane);
        float2 v2 = __ldg(p2 + lane), v3 = __ldg(p3 + lane);
        a0 += w0 * v0.x + w1 * v1.x + w2 * v2.x + w3 * v3.x;
        a1 += w0 * v0.y + w1 * v1.y + w2 * v2.y + w3 * v3.y;
    }
    for (; j < end; j++) {
        int c = __ldg(cols + j);
        float w = __ldg(ws + j);
        const float2* p = (c < N_DRUG) ? xa + (size_t)c * 32 : xb + (size_t)(c - N_DRUG) * 32;
        float2 v = __ldg(p + lane);
        a0 += w * v.x;
        a1 += w * v.y;
    }
    return make_float2(a0, a1);
}

// -------- mega kernel: SpMM (4 rows) + noise + l2n + recurrence, one warp per pair r --------
// lane covers columns (2*lane, 2*lane+1)
__global__ void mega_kernel(const int* __restrict__ rowptr,
                            const int* __restrict__ cols,
                            const float* __restrict__ ws,
                            const float* __restrict__ src,   // cur (drug;dis) for rr/dd
                            const float* __restrict__ rdA,   // rd-graph source, first 100k rows
                            const float* __restrict__ rdB,   // rd-graph source, last 100k rows
                            float* __restrict__ dst,         // next cur buffer
                            float* __restrict__ out,
                            uint32_t k0, uint32_t k1, int slot, int write_next) {
    int r = (blockIdx.x * blockDim.x + threadIdx.x) >> 5;
    int lane = threadIdx.x & 31;
    if (r >= N_DRUG) return;

    const float2* xd = (const float2*)src;
    const float2* xs = (const float2*)(src + FLAT_DRUG);
    const float2* ra = (const float2*)rdA;
    const float2* rb = (const float2*)rdB;

    int s_rr = __ldg(rowptr + r),                 e_rr = __ldg(rowptr + r + 1);
    int s_dd = __ldg(rowptr + N_DRUG + r),        e_dd = __ldg(rowptr + N_DRUG + r + 1);
    int s_r1 = __ldg(rowptr + 200000 + r),        e_r1 = __ldg(rowptr + 200000 + r + 1);
    int s_r2 = __ldg(rowptr + 300000 + r),        e_r2 = __ldg(rowptr + 300000 + r + 1);

    float2 d0 = gather_row(cols, ws, s_rr, e_rr, lane, xd, xd);   // rr cols < 100k always
    float2 s0 = gather_row(cols, ws, s_dd, e_dd, lane, xs, xs);   // dd cols < 100k always
    float2 r0d = gather_row(cols, ws, s_r1, e_r1, lane, ra, rb);  // rd combined cols
    float2 r0s = gather_row(cols, ws, s_r2, e_r2, lane, ra, rb);

    // threefry noise: counters = flat element index (drug half: r*64+c, dis half: +FLAT_DRUG)
    uint32_t id0 = (uint32_t)(r * HID + 2 * lane);
    float nd0 = u01(rbits32(k0, k1, id0));
    float nd1 = u01(rbits32(k0, k1, id0 + 1u));
    float ns0 = u01(rbits32(k0, k1, id0 + (uint32_t)FLAT_DRUG));
    float ns1 = u01(rbits32(k0, k1, id0 + 1u + (uint32_t)FLAT_DRUG));

    float scnd = 0.1f / fmaxf(sqrtf(wsum(nd0*nd0 + nd1*nd1)), 1e-12f);
    float scns = 0.1f / fmaxf(sqrtf(wsum(ns0*ns0 + ns1*ns1)), 1e-12f);
    float invd0 = 1.0f / fmaxf(sqrtf(wsum(d0.x*d0.x + d0.y*d0.y)), 1e-12f);
    float invs0 = 1.0f / fmaxf(sqrtf(wsum(s0.x*s0.x + s0.y*s0.y)), 1e-12f);

    float2 rnd, rns;
    rnd.x = r0d.x + sgnf(r0d.x) * nd0 * scnd;
    rnd.y = r0d.y + sgnf(r0d.y) * nd1 * scnd;
    rns.x = r0s.x + sgnf(r0s.x) * ns0 * scns;
    rns.y = r0s.y + sgnf(r0s.y) * ns1 * scns;

    float invrd = 1.0f / fmaxf(sqrtf(wsum(rnd.x*rnd.x + rnd.y*rnd.y)), 1e-12f);
    float invrs = 1.0f / fmaxf(sqrtf(wsum(rns.x*rns.x + rns.y*rns.y)), 1e-12f);

    // rd_stack slot writes: OFF_STACK is an ODD float offset -> SCALAR stores only
    {
        float* stkD = out + OFF_STACK + (size_t)r * 256 + slot * 64 + 2 * lane;
        float* stkS = out + OFF_STACK + (size_t)(r + N_DRUG) * 256 + slot * 64 + 2 * lane;
        stkD[0] = rnd.x * invrd;
        stkD[1] = rnd.y * invrd;
        stkS[0] = rns.x * invrs;
        stkS[1] = rns.y * invrs;
    }

    // drugE / disE accumulators (RMW; even float offsets -> float2 OK)
    float2* accD = (float2*)(out + OFF_DRUGE) + r * 32 + lane;
    float2* accS = (float2*)(out + OFF_DISE)  + r * 32 + lane;
    float2 ad = *accD, as = *accS;
    ad.x += d0.x * invd0; ad.y += d0.y * invd0;
    as.x += s0.x * invs0; as.y += s0.y * invs0;
    *accD = ad; *accS = as;

    // recurrence: cur_next = 0.5*prop + 0.5*rnew (skip on last layer)
    if (write_next) {
        float2* dD = (float2*)dst + r * 32 + lane;
        float2* dS = (float2*)(dst + FLAT_DRUG) + r * 32 + lane;
        *dD = make_float2(0.5f * d0.x + 0.5f * rnd.x, 0.5f * d0.y + 0.5f * rnd.y);
        *dS = make_float2(0.5f * s0.x + 0.5f * rns.x, 0.5f * s0.y + 0.5f * rns.y);
    }
}

__global__ void final_kernel(const float* __restrict__ drug, const float* __restrict__ dis,
                             float* __restrict__ out) {
    int idx = blockIdx.x * blockDim.x + threadIdx.x;
    if (idx >= FLAT_ALL) return;
    float e = (idx < FLAT_DRUG) ? drug[idx] : dis[idx - FLAT_DRUG];
    float Ev = out[idx] * 0.25f;
    out[idx] = Ev;
    out[OFF_ALL + idx] = 0.5f * e + 0.5f * Ev;
    out[OFF_RD + idx] = e;
    if (idx == 0) out[OFF_META] = 0.0f;
}

// -------- host threefry (fold_in key derivation) --------
static inline void h_tf2x32(uint32_t k0, uint32_t k1, uint32_t x0, uint32_t x1,
                            uint32_t& o0, uint32_t& o1) {
    uint32_t k2 = k0 ^ k1 ^ 0x1BD11BDAu;
#define HROT(v, r) (((v) << (r)) | ((v) >> (32 - (r))))
#define HTFR(r) { x0 += x1; x1 = HROT(x1, r); x1 ^= x0; }
    x0 += k0; x1 += k1;
    HTFR(13) HTFR(15) HTFR(26) HTFR(6)
    x0 += k1; x1 += k2 + 1u;
    HTFR(17) HTFR(29) HTFR(16) HTFR(24)
    x0 += k2; x1 += k0 + 2u;
    HTFR(13) HTFR(15) HTFR(26) HTFR(6)
    x0 += k0; x1 += k1 + 3u;
    HTFR(17) HTFR(29) HTFR(16) HTFR(24)
    x0 += k1; x1 += k2 + 4u;
    HTFR(13) HTFR(15) HTFR(26) HTFR(6)
    x0 += k2; x1 += k0 + 5u;
#undef HTFR
#undef HROT
    o0 = x0; o1 = x1;
}

extern "C" void kernel_launch(void* const* d_in, const int* in_sizes, int n_in,
                              void* d_out, int out_size) {
    const float* drug_emb = (const float*)d_in[0];
    const float* dis_emb  = (const float*)d_in[1];
    const float* Wr = (const float*)d_in[2];
    const float* br = (const float*)d_in[3];
    const float* Wd = (const float*)d_in[4];
    const float* bd = (const float*)d_in[5];
    const int*   rr_row = (const int*)d_in[6];
    const int*   rr_col = (const int*)d_in[7];
    const float* rr_val = (const float*)d_in[8];
    const int*   dd_row = (const int*)d_in[9];
    const int*   dd_col = (const int*)d_in[10];
    const float* dd_val = (const float*)d_in[11];
    const int*   rd_row = (const int*)d_in[12];
    const int*   rd_col = (const int*)d_in[13];
    const float* rd_val = (const float*)d_in[14];
    float* out = (float*)d_out;

    float *cur0, *cur1, *deg, *ws;
    int *cnt, *cursor, *rowptr, *bsum, *cols;
    cudaGetSymbolAddress((void**)&cur0,   g_cur0);
    cudaGetSymbolAddress((void**)&cur1,   g_cur1);
    cudaGetSymbolAddress((void**)&deg,    g_deg);
    cudaGetSymbolAddress((void**)&cnt,    g_cnt);
    cudaGetSymbolAddress((void**)&cursor, g_cursor);
    cudaGetSymbolAddress((void**)&rowptr, g_rowptr);
    cudaGetSymbolAddress((void**)&bsum,   g_bsum);
    cudaGetSymbolAddress((void**)&cols,   g_cols);
    cudaGetSymbolAddress((void**)&ws,     g_ws);

    float* rr_dr = deg;
    float* rr_dc = deg + N_DRUG;
    float* dd_dr = deg + 2 * N_DRUG;
    float* dd_dc = deg + 2 * N_DRUG + N_DIS;
    float* rd_dr = deg + 2 * N_DRUG + 2 * N_DIS;
    float* rd_dc = deg + 2 * N_DRUG + 2 * N_DIS + N_RDN;

    const int B = 256;

    // ---- CSR build ----
    cudaMemsetAsync(deg, 0, sizeof(float) * (2*N_DRUG + 2*N_DIS + 2*N_RDN), 0);
    cudaMemsetAsync(cnt, 0, sizeof(int) * NROWS, 0);

    deg_cnt_kernel<<<(ERR_ + B - 1) / B, B>>>(rr_row, rr_col, rr_val, ERR_, rr_dr, rr_dc, cnt);
    deg_cnt_kernel<<<(EDD_ + B - 1) / B, B>>>(dd_row, dd_col, dd_val, EDD_, dd_dr, dd_dc, cnt + N_DRUG);
    deg_cnt_kernel<<<(ERD_ + B - 1) / B, B>>>(rd_row, rd_col, rd_val, ERD_, rd_dr, rd_dc, cnt + N_DRUG + N_DIS);

    scan1_kernel<<<NBLK1, 1024>>>(cnt, rowptr, bsum);
    scan2_kernel<<<1, 512>>>(bsum, NBLK1);
    scan3_kernel<<<NBLK1, 1024>>>(rowptr, bsum);
    cursor_init_kernel<<<(NROWS + 1023) / 1024, 1024>>>(rowptr, cursor);

    fill_kernel<<<(ERR_ + B - 1) / B, B>>>(rr_row, rr_col, rr_val, ERR_, rr_dr, rr_dc,
                                           cursor, cols, ws);
    fill_kernel<<<(EDD_ + B - 1) / B, B>>>(dd_row, dd_col, dd_val, EDD_, dd_dr, dd_dc,
                                           cursor + N_DRUG, cols, ws);
    fill_kernel<<<(ERD_ + B - 1) / B, B>>>(rd_row, rd_col, rd_val, ERD_, rd_dr, rd_dc,
                                           cursor + N_DRUG + N_DIS, cols, ws);

    // ---- init: gate -> cur0 + drugE/disE accum + stack slot 0 ----
    gate_kernel<<<(N_DRUG * 32) / B, B>>>(drug_emb, Wr, br, N_DRUG,
                                          cur0, out + OFF_DRUGE, out + OFF_STACK);
    gate_kernel<<<(N_DIS * 32) / B, B>>>(dis_emb, Wd, bd, N_DIS,
                                         cur0 + FLAT_DRUG, out + OFF_DISE,
                                         out + OFF_STACK + (size_t)N_DRUG * 256);

    // ---- layers (ping-pong cur buffers; layer 0 rd-source = raw embeddings) ----
    float* bufs[2] = {cur0, cur1};
    for (int i = 0; i < 3; i++) {
        uint32_t kk0, kk1;
        h_tf2x32(0u, 1u, 0u, (uint32_t)i, kk0, kk1);  // fold_in(key(1), i)

        float* src = bufs[i & 1];
        float* dst = bufs[(i + 1) & 1];
        const float* rdA = (i == 0) ? drug_emb : src;
        const float* rdB = (i == 0) ? dis_emb  : src + FLAT_DRUG;
        mega_kernel<<<(N_DRUG * 32 + B - 1) / B, B>>>(rowptr, cols, ws, src, rdA, rdB,
                                                      dst, out, kk0, kk1, i + 1,
                                                      (i < 2) ? 1 : 0);
    }

    final_kernel<<<(FLAT_ALL + B - 1) / B, B>>>(drug_emb, dis_emb, out);
}